// round 3
// baseline (speedup 1.0000x reference)
#include <cuda_runtime.h>

#define NB      4
#define RB      72          // NB * 18 rows per CTA
#define THREADS 256
#define TSTEPS  128
#define NNODE   18
#define DIMX    32
#define HIDN    64
#define STF     132         // feature-buffer row stride (floats), padded
#define STH     68          // hidden-state row stride
#define STX     36          // x-tile row stride
#define NBLK    128         // grid: 512 / NB

typedef unsigned long long u64;

// ---------------- packed f32x2 helpers ----------------
__device__ __forceinline__ u64 pk2(float a, float b) {
    u64 r;
    asm("mov.b64 %0, {%1, %2};" : "=l"(r)
        : "r"(__float_as_uint(a)), "r"(__float_as_uint(b)));
    return r;
}
__device__ __forceinline__ float2 up2(u64 v) {
    unsigned lo, hi;
    asm("mov.b64 {%0, %1}, %2;" : "=r"(lo), "=r"(hi) : "l"(v));
    return make_float2(__uint_as_float(lo), __uint_as_float(hi));
}
__device__ __forceinline__ void fma2(u64 &d, u64 a, u64 b) {
    asm("fma.rn.f32x2 %0, %1, %2, %0;" : "+l"(d) : "l"(a), "l"(b));
}

__device__ __forceinline__ float sigm(float v) {
    return 1.f / (1.f + __expf(-v));
}
__device__ __forceinline__ float tanh_(float v) {
    float e = __expf(2.f * v);
    return 1.f - 2.f / (e + 1.f);
}

// ---------------- shared memory layout ----------------
struct Smem {
    float S[2][NNODE * NNODE];  // supports
    float X[RB * STX];          // x tile for current t
    float hA[RB * STH];
    float hB[RB * STH];
    float Z[RB * STF];          // concat input
    float Da[RB * STF];         // Chebyshev x1
    float Db[RB * STF];         // Chebyshev x2
    float OUT[RB * STF];        // gate output (r|u), sigmoided
    float CB[RB * STH];         // candidate output, tanh'd
};
// sizeof(Smem) = 223776 bytes  (< 227 KB limit, 1 CTA/SM)

// ---------------- spmm: dst = S_sup @ src  (or 2*S@src - Zsub) ----------------
__device__ __forceinline__ void spmm(const float* __restrict__ Ssup,
                                     const float* __restrict__ src,
                                     float* __restrict__ dst,
                                     const float* __restrict__ zsub,
                                     int CC, int rbase, int bloc, int nloc,
                                     int colg)
{
    int c0 = 4 * colg;
    if (c0 >= CC) return;
    const float* srcb = src + bloc * NNODE * STF + c0;
    u64 a0[9], a1[9];
#pragma unroll
    for (int i = 0; i < 9; i++) { a0[i] = 0; a1[i] = 0; }
#pragma unroll 1
    for (int mm = 0; mm < NNODE; mm++) {
        ulonglong2 z = *(const ulonglong2*)(srcb + mm * STF);
#pragma unroll
        for (int i = 0; i < 9; i++) {
            float s = Ssup[(nloc + i) * NNODE + mm];
            u64 s2 = pk2(s, s);
            fma2(a0[i], s2, z.x);
            fma2(a1[i], s2, z.y);
        }
    }
#pragma unroll
    for (int i = 0; i < 9; i++) {
        float2 p0 = up2(a0[i]), p1 = up2(a1[i]);
        float4 o;
        if (zsub) {
            float4 zz = *(const float4*)(zsub + (rbase + i) * STF + c0);
            o = make_float4(2.f * p0.x - zz.x, 2.f * p0.y - zz.y,
                            2.f * p1.x - zz.z, 2.f * p1.y - zz.w);
        } else {
            o = make_float4(p0.x, p0.y, p1.x, p1.y);
        }
        *(float4*)(dst + (rbase + i) * STF + c0) = o;
    }
}

// ---------------- gate GEMM block: acc[18] += feat[72,CC] @ W[CC,128] tile ----
__device__ __forceinline__ void gemm_gate(const float* __restrict__ feat,
                                          const float* __restrict__ W,
                                          int CC, int colg, int rbase,
                                          u64 acc[18])
{
    const float* wp = W + 4 * colg;
#pragma unroll 2
    for (int k = 0; k < CC; k += 4) {
        const float* wk = wp + (size_t)k * 128;
        ulonglong2 w0 = __ldg((const ulonglong2*)(wk));
        ulonglong2 w1 = __ldg((const ulonglong2*)(wk + 128));
        ulonglong2 w2 = __ldg((const ulonglong2*)(wk + 256));
        ulonglong2 w3 = __ldg((const ulonglong2*)(wk + 384));
#pragma unroll
        for (int i = 0; i < 9; i++) {
            float4 f = *(const float4*)(feat + (rbase + i) * STF + k);
            u64 fx = pk2(f.x, f.x);
            fma2(acc[2 * i], fx, w0.x); fma2(acc[2 * i + 1], fx, w0.y);
            u64 fy = pk2(f.y, f.y);
            fma2(acc[2 * i], fy, w1.x); fma2(acc[2 * i + 1], fy, w1.y);
            u64 fz = pk2(f.z, f.z);
            fma2(acc[2 * i], fz, w2.x); fma2(acc[2 * i + 1], fz, w2.y);
            u64 fw = pk2(f.w, f.w);
            fma2(acc[2 * i], fw, w3.x); fma2(acc[2 * i + 1], fw, w3.y);
        }
    }
}

// ---------------- cand GEMM block: acc[9] += feat[72,CC] @ W[CC,64] tile -----
__device__ __forceinline__ void gemm_cand(const float* __restrict__ feat,
                                          const float* __restrict__ W,
                                          int CC, int colg, int rbase,
                                          u64 acc[9])
{
    const float* wp = W + 2 * colg;
#pragma unroll 2
    for (int k = 0; k < CC; k += 4) {
        const float* wk = wp + (size_t)k * 64;
        u64 w0 = __ldg((const u64*)(wk));
        u64 w1 = __ldg((const u64*)(wk + 64));
        u64 w2 = __ldg((const u64*)(wk + 128));
        u64 w3 = __ldg((const u64*)(wk + 192));
#pragma unroll
        for (int i = 0; i < 9; i++) {
            float4 f = *(const float4*)(feat + (rbase + i) * STF + k);
            fma2(acc[i], pk2(f.x, f.x), w0);
            fma2(acc[i], pk2(f.y, f.y), w1);
            fma2(acc[i], pk2(f.z, f.z), w2);
            fma2(acc[i], pk2(f.w, f.w), w3);
        }
    }
}

// ---------------- main persistent kernel ----------------
__global__ void __launch_bounds__(THREADS, 1)
dcrnn_kernel(const float* __restrict__ x,   const float* __restrict__ sup,
             const float* __restrict__ wg0, const float* __restrict__ bg0,
             const float* __restrict__ wc0, const float* __restrict__ bc0,
             const float* __restrict__ wg1, const float* __restrict__ bg1,
             const float* __restrict__ wc1, const float* __restrict__ bc1,
             const float* __restrict__ fcw, const float* __restrict__ fcb,
             float* __restrict__ out)
{
    extern __shared__ char smraw[];
    Smem& sm = *reinterpret_cast<Smem*>(smraw);

    const int tid   = threadIdx.x;
    const int bbase = blockIdx.x * NB;
    const int rowg  = tid & 7;
    const int colg  = tid >> 3;
    const int rbase = rowg * 9;
    const int bloc  = rowg >> 1;          // local batch of this thread's rows
    const int nloc  = 9 * (rowg & 1);     // node offset of this thread's rows

    // init
    for (int i = tid; i < 2 * NNODE * NNODE; i += THREADS)
        ((float*)sm.S)[i] = sup[i];
    for (int i = tid; i < RB * STH; i += THREADS) { sm.hA[i] = 0.f; sm.hB[i] = 0.f; }
    __syncthreads();

    for (int t = 0; t < TSTEPS; t++) {
        // ---- load x tile: X[r][0:32] = x[b, t, n, :] ----
        for (int j = tid; j < RB * 8; j += THREADS) {
            int r = j >> 3, d4 = j & 7;
            int b = bbase + r / NNODE;
            int n = r - NNODE * (r / NNODE);
            float4 v = *(const float4*)(x +
                (((size_t)b * TSTEPS + t) * NNODE + n) * DIMX + 4 * d4);
            *(float4*)(sm.X + r * STX + 4 * d4) = v;
        }
        __syncthreads();

        for (int cell = 0; cell < 2; cell++) {
            const int CC = cell ? 128 : 96;
            const float* WG = cell ? wg1 : wg0;
            const float* BG = cell ? bg1 : bg0;
            const float* WC = cell ? wc1 : wc0;
            const float* BC = cell ? bc1 : bc0;
            float* H = cell ? sm.hB : sm.hA;

            // ============ GATE dconv ============
            // build Z = [input, H]
            if (cell == 0) {
                for (int j = tid; j < RB * 24; j += THREADS) {
                    int r = j / 24, c = 4 * (j - 24 * r);
                    float4 v = (c < DIMX)
                        ? *(const float4*)(sm.X + r * STX + c)
                        : *(const float4*)(sm.hA + r * STH + (c - DIMX));
                    *(float4*)(sm.Z + r * STF + c) = v;
                }
            } else {
                for (int j = tid; j < RB * 32; j += THREADS) {
                    int r = j >> 5, c = 4 * (j & 31);
                    float4 v = (c < HIDN)
                        ? *(const float4*)(sm.hA + r * STH + c)
                        : *(const float4*)(sm.hB + r * STH + (c - HIDN));
                    *(float4*)(sm.Z + r * STF + c) = v;
                }
            }
            __syncthreads();

            {
                u64 ga[18];
#pragma unroll
                for (int q = 0; q < 18; q++) ga[q] = 0;
                for (int m = 0; m < 5; m++) {
                    const float* feat;
                    if (m == 0) feat = sm.Z;
                    else {
                        int s = (m - 1) >> 1;
                        int second = (m - 1) & 1;
                        const float* src = second ? sm.Da : sm.Z;
                        float* dst = second ? sm.Db : sm.Da;
                        spmm(sm.S[s], src, dst, second ? sm.Z : (const float*)0,
                             CC, rbase, bloc, nloc, colg);
                        __syncthreads();
                        feat = dst;
                    }
                    gemm_gate(feat, WG + (size_t)m * CC * 128, CC, colg, rbase, ga);
                }
                // writeout: sigmoid(acc + bias)
                float4 bv = *(const float4*)(BG + 4 * colg);
#pragma unroll
                for (int i = 0; i < 9; i++) {
                    float2 p0 = up2(ga[2 * i]), p1 = up2(ga[2 * i + 1]);
                    float4 o;
                    o.x = sigm(p0.x + bv.x); o.y = sigm(p0.y + bv.y);
                    o.z = sigm(p1.x + bv.z); o.w = sigm(p1.y + bv.w);
                    *(float4*)(sm.OUT + (rbase + i) * STF + 4 * colg) = o;
                }
            }
            __syncthreads();

            // ============ CANDIDATE dconv ============
            // build Z = [input, r * H]
            if (cell == 0) {
                for (int j = tid; j < RB * 24; j += THREADS) {
                    int r = j / 24, c = 4 * (j - 24 * r);
                    float4 v;
                    if (c < DIMX) {
                        v = *(const float4*)(sm.X + r * STX + c);
                    } else {
                        float4 h4 = *(const float4*)(sm.hA + r * STH + (c - DIMX));
                        float4 rr = *(const float4*)(sm.OUT + r * STF + (c - DIMX));
                        v = make_float4(h4.x * rr.x, h4.y * rr.y,
                                        h4.z * rr.z, h4.w * rr.w);
                    }
                    *(float4*)(sm.Z + r * STF + c) = v;
                }
            } else {
                for (int j = tid; j < RB * 32; j += THREADS) {
                    int r = j >> 5, c = 4 * (j & 31);
                    float4 v;
                    if (c < HIDN) {
                        v = *(const float4*)(sm.hA + r * STH + c);
                    } else {
                        float4 h4 = *(const float4*)(sm.hB + r * STH + (c - HIDN));
                        float4 rr = *(const float4*)(sm.OUT + r * STF + (c - HIDN));
                        v = make_float4(h4.x * rr.x, h4.y * rr.y,
                                        h4.z * rr.z, h4.w * rr.w);
                    }
                    *(float4*)(sm.Z + r * STF + c) = v;
                }
            }
            __syncthreads();

            {
                u64 ca[9];
#pragma unroll
                for (int q = 0; q < 9; q++) ca[q] = 0;
                for (int m = 0; m < 5; m++) {
                    const float* feat;
                    if (m == 0) feat = sm.Z;
                    else {
                        int s = (m - 1) >> 1;
                        int second = (m - 1) & 1;
                        const float* src = second ? sm.Da : sm.Z;
                        float* dst = second ? sm.Db : sm.Da;
                        spmm(sm.S[s], src, dst, second ? sm.Z : (const float*)0,
                             CC, rbase, bloc, nloc, colg);
                        __syncthreads();
                        feat = dst;
                    }
                    gemm_cand(feat, WC + (size_t)m * CC * 64, CC, colg, rbase, ca);
                }
                // writeout: tanh(acc + bias)
                float2 bv = *(const float2*)(BC + 2 * colg);
#pragma unroll
                for (int i = 0; i < 9; i++) {
                    float2 p = up2(ca[i]);
                    float2 o = make_float2(tanh_(p.x + bv.x), tanh_(p.y + bv.y));
                    *(float2*)(sm.CB + (rbase + i) * STH + 2 * colg) = o;
                }
            }
            __syncthreads();

            // ============ GRU update: h = c + u*(h - c) ============
            for (int j = tid; j < RB * 32; j += THREADS) {
                int r = j >> 5, c = 2 * (j & 31);
                float2 h2 = *(const float2*)(H + r * STH + c);
                float2 c2 = *(const float2*)(sm.CB + r * STH + c);
                float2 u2 = *(const float2*)(sm.OUT + r * STF + HIDN + c);
                float2 nh = make_float2(c2.x + u2.x * (h2.x - c2.x),
                                        c2.y + u2.y * (h2.y - c2.y));
                *(float2*)(H + r * STH + c) = nh;
            }
            __syncthreads();
        } // cell
    } // t

    // ---- epilogue: logits = relu(hB) @ fc_w + fc_b; out[b] = max over nodes ----
    if (tid < RB) {
        float acc = fcb[0];
#pragma unroll
        for (int c = 0; c < HIDN; c++)
            acc += fmaxf(sm.hB[tid * STH + c], 0.f) * fcw[c];
        sm.Z[tid] = acc;
    }
    __syncthreads();
    if (tid < NB) {
        float mx = -3.4e38f;
#pragma unroll
        for (int n = 0; n < NNODE; n++)
            mx = fmaxf(mx, sm.Z[tid * NNODE + n]);
        out[bbase + tid] = mx;
    }
}

extern "C" void kernel_launch(void* const* d_in, const int* in_sizes, int n_in,
                              void* d_out, int out_size)
{
    (void)in_sizes; (void)n_in; (void)out_size;
    const size_t shbytes = sizeof(Smem);
    cudaFuncSetAttribute(dcrnn_kernel,
                         cudaFuncAttributeMaxDynamicSharedMemorySize,
                         (int)shbytes);
    dcrnn_kernel<<<NBLK, THREADS, shbytes>>>(
        (const float*)d_in[0],  (const float*)d_in[1],
        (const float*)d_in[2],  (const float*)d_in[3],
        (const float*)d_in[4],  (const float*)d_in[5],
        (const float*)d_in[6],  (const float*)d_in[7],
        (const float*)d_in[8],  (const float*)d_in[9],
        (const float*)d_in[10], (const float*)d_in[11],
        (float*)d_out);
}

// round 4
// speedup vs baseline: 1.0405x; 1.0405x over previous
#include <cuda_runtime.h>

#define NB      4
#define RB      72          // NB * 18 rows per CTA
#define THREADS 512
#define TSTEPS  128
#define NNODE   18
#define DIMX    32
#define HIDN    64
#define STF     132         // feature-buffer row stride (floats), padded
#define STH     68          // hidden-state row stride
#define STX     36          // x-tile row stride
#define NBLK    128         // grid: 512 / NB
#define STS2    24          // St2 row stride in float2

typedef unsigned long long u64;

// ---------------- packed f32x2 helpers ----------------
__device__ __forceinline__ u64 pk2(float a, float b) {
    u64 r;
    asm("mov.b64 %0, {%1, %2};" : "=l"(r)
        : "r"(__float_as_uint(a)), "r"(__float_as_uint(b)));
    return r;
}
__device__ __forceinline__ float2 up2(u64 v) {
    unsigned lo, hi;
    asm("mov.b64 {%0, %1}, %2;" : "=r"(lo), "=r"(hi) : "l"(v));
    return make_float2(__uint_as_float(lo), __uint_as_float(hi));
}
__device__ __forceinline__ void fma2(u64 &d, u64 a, u64 b) {
    asm("fma.rn.f32x2 %0, %1, %2, %0;" : "+l"(d) : "l"(a), "l"(b));
}
__device__ __forceinline__ void add2(u64 &d, u64 a) {
    asm("add.rn.f32x2 %0, %0, %1;" : "+l"(d) : "l"(a));
}

__device__ __forceinline__ float sigm(float v) {
    return 1.f / (1.f + __expf(-v));
}
__device__ __forceinline__ float tanh_(float v) {
    float e = __expf(2.f * v);
    return 1.f - 2.f / (e + 1.f);
}

// ---------------- shared memory layout ----------------
struct __align__(16) Smem {
    float2 St2[2][NNODE * STS2]; // transposed supports, duplicated pairs
    float X[RB * STX];          // x tile for current t
    float hA[RB * STH];
    float hB[RB * STH];
    float Z[RB * STF];          // concat input
    float Da[RB * STF];         // Chebyshev x1 (doubles as reduction scratch)
    float Db[RB * STF];         // Chebyshev x2
    float OUT[RB * STF];        // gate output (r|u), sigmoided
    float CB[RB * STH];         // candidate output, tanh'd
};
// sizeof(Smem) = 228096 bytes  (<= 227 KB dyn-smem limit, 1 CTA/SM)

// ---------------- spmm (2 cols/thread): dst = S @ src  (or 2*S@src - Zsub) ----
__device__ __forceinline__ void spmm2(const float2* __restrict__ St,
                                      const float* __restrict__ src,
                                      float* __restrict__ dst,
                                      const float* __restrict__ zsub,
                                      int CC, int rbase, int bloc, int nlo,
                                      int c0)
{
    if (c0 >= CC) return;
    const float* srcb = src + bloc * NNODE * STF + c0;
    u64 a[9];
#pragma unroll
    for (int i = 0; i < 9; i++) a[i] = 0;
#pragma unroll 1
    for (int mm = 0; mm < NNODE; mm++) {
        u64 z = *(const u64*)(srcb + mm * STF);
        const float2* sp = St + mm * STS2 + nlo;
        ulonglong2 p01 = *(const ulonglong2*)(sp);
        ulonglong2 p23 = *(const ulonglong2*)(sp + 2);
        ulonglong2 p45 = *(const ulonglong2*)(sp + 4);
        ulonglong2 p67 = *(const ulonglong2*)(sp + 6);
        u64        p8  = *(const u64*)(sp + 8);
        fma2(a[0], p01.x, z); fma2(a[1], p01.y, z);
        fma2(a[2], p23.x, z); fma2(a[3], p23.y, z);
        fma2(a[4], p45.x, z); fma2(a[5], p45.y, z);
        fma2(a[6], p67.x, z); fma2(a[7], p67.y, z);
        fma2(a[8], p8,    z);
    }
#pragma unroll
    for (int i = 0; i < 9; i++) {
        float2 p = up2(a[i]);
        float2 o;
        if (zsub) {
            float2 zz = *(const float2*)(zsub + (rbase + i) * STF + c0);
            o = make_float2(2.f * p.x - zz.x, 2.f * p.y - zz.y);
        } else {
            o = p;
        }
        *(float2*)(dst + (rbase + i) * STF + c0) = o;
    }
}

// ---------------- gate GEMM k-slice: acc += feat[rows, kbeg:kend] @ W tile ----
__device__ __forceinline__ void gemm_gate(const float* __restrict__ feat,
                                          const float* __restrict__ W,
                                          int kbeg, int kend, int colg, int rbase,
                                          u64 acc[18])
{
    const float* wp = W + 4 * colg;
#pragma unroll 2
    for (int k = kbeg; k < kend; k += 4) {
        const float* wk = wp + (size_t)k * 128;
        ulonglong2 w0 = __ldg((const ulonglong2*)(wk));
        ulonglong2 w1 = __ldg((const ulonglong2*)(wk + 128));
        ulonglong2 w2 = __ldg((const ulonglong2*)(wk + 256));
        ulonglong2 w3 = __ldg((const ulonglong2*)(wk + 384));
#pragma unroll
        for (int i = 0; i < 9; i++) {
            float4 f = *(const float4*)(feat + (rbase + i) * STF + k);
            u64 fx = pk2(f.x, f.x);
            fma2(acc[2 * i], fx, w0.x); fma2(acc[2 * i + 1], fx, w0.y);
            u64 fy = pk2(f.y, f.y);
            fma2(acc[2 * i], fy, w1.x); fma2(acc[2 * i + 1], fy, w1.y);
            u64 fz = pk2(f.z, f.z);
            fma2(acc[2 * i], fz, w2.x); fma2(acc[2 * i + 1], fz, w2.y);
            u64 fw = pk2(f.w, f.w);
            fma2(acc[2 * i], fw, w3.x); fma2(acc[2 * i + 1], fw, w3.y);
        }
    }
}

// ---------------- cand GEMM k-slice: acc += feat[rows, kbeg:kend] @ W tile ----
__device__ __forceinline__ void gemm_cand(const float* __restrict__ feat,
                                          const float* __restrict__ W,
                                          int kbeg, int kend, int colg, int rbase,
                                          u64 acc[9])
{
    const float* wp = W + 2 * colg;
#pragma unroll 2
    for (int k = kbeg; k < kend; k += 4) {
        const float* wk = wp + (size_t)k * 64;
        u64 w0 = __ldg((const u64*)(wk));
        u64 w1 = __ldg((const u64*)(wk + 64));
        u64 w2 = __ldg((const u64*)(wk + 128));
        u64 w3 = __ldg((const u64*)(wk + 192));
#pragma unroll
        for (int i = 0; i < 9; i++) {
            float4 f = *(const float4*)(feat + (rbase + i) * STF + k);
            fma2(acc[i], pk2(f.x, f.x), w0);
            fma2(acc[i], pk2(f.y, f.y), w1);
            fma2(acc[i], pk2(f.z, f.z), w2);
            fma2(acc[i], pk2(f.w, f.w), w3);
        }
    }
}

// ---------------- main persistent kernel ----------------
__global__ void __launch_bounds__(THREADS, 1)
dcrnn_kernel(const float* __restrict__ x,   const float* __restrict__ sup,
             const float* __restrict__ wg0, const float* __restrict__ bg0,
             const float* __restrict__ wc0, const float* __restrict__ bc0,
             const float* __restrict__ wg1, const float* __restrict__ bg1,
             const float* __restrict__ wc1, const float* __restrict__ bc1,
             const float* __restrict__ fcw, const float* __restrict__ fcb,
             float* __restrict__ out)
{
    extern __shared__ char smraw[];
    Smem& sm = *reinterpret_cast<Smem*>(smraw);

    const int tid   = threadIdx.x;
    const int bbase = blockIdx.x * NB;
    const int rowg  = tid & 7;            // 8 row groups of 9 rows
    const int colg  = (tid >> 3) & 31;    // 32 col groups (gemm)
    const int khalf = tid >> 8;           // k-slice half (gemm)
    const int cg2   = tid >> 3;           // 64 col-pair groups (spmm)
    const int c0    = 2 * cg2;
    const int rbase = rowg * 9;
    const int bloc  = rowg >> 1;          // local batch of this thread's rows
    const int nloc  = 9 * (rowg & 1);     // node offset of this thread's rows
    const int nlo   = (rowg & 1) ? 12 : 0; // St2 lane base

    u64* const scr = (u64*)sm.Da;         // reduction scratch (Da reused)

    // init: transpose + duplicate supports into St2
    for (int i = tid; i < 2 * NNODE * NNODE; i += THREADS) {
        int s = i / (NNODE * NNODE);
        int rem = i - s * NNODE * NNODE;
        int n = rem / NNODE;              // row of S
        int m = rem - n * NNODE;          // col of S
        float v = sup[i];
        int lane = (n < 9) ? n : (12 + n - 9);
        sm.St2[s][m * STS2 + lane] = make_float2(v, v);
    }
    for (int i = tid; i < RB * STH; i += THREADS) { sm.hA[i] = 0.f; sm.hB[i] = 0.f; }
    __syncthreads();

    for (int t = 0; t < TSTEPS; t++) {
        // ---- load x tile: X[r][0:32] = x[b, t, n, :] ----
        for (int j = tid; j < RB * 8; j += THREADS) {
            int r = j >> 3, d4 = j & 7;
            int b = bbase + r / NNODE;
            int n = r - NNODE * (r / NNODE);
            float4 v = *(const float4*)(x +
                (((size_t)b * TSTEPS + t) * NNODE + n) * DIMX + 4 * d4);
            *(float4*)(sm.X + r * STX + 4 * d4) = v;
        }
        __syncthreads();

        for (int cell = 0; cell < 2; cell++) {
            const int CC  = cell ? 128 : 96;
            const int CCH = CC >> 1;
            const int kbeg = khalf * CCH;
            const int kend = kbeg + CCH;
            const float* WG = cell ? wg1 : wg0;
            const float* BG = cell ? bg1 : bg0;
            const float* WC = cell ? wc1 : wc0;
            const float* BC = cell ? bc1 : bc0;
            float* H = cell ? sm.hB : sm.hA;

            // ============ GATE dconv ============
            if (cell == 0) {
                for (int j = tid; j < RB * 24; j += THREADS) {
                    int r = j / 24, c = 4 * (j - 24 * r);
                    float4 v = (c < DIMX)
                        ? *(const float4*)(sm.X + r * STX + c)
                        : *(const float4*)(sm.hA + r * STH + (c - DIMX));
                    *(float4*)(sm.Z + r * STF + c) = v;
                }
            } else {
                for (int j = tid; j < RB * 32; j += THREADS) {
                    int r = j >> 5, c = 4 * (j & 31);
                    float4 v = (c < HIDN)
                        ? *(const float4*)(sm.hA + r * STH + c)
                        : *(const float4*)(sm.hB + r * STH + (c - HIDN));
                    *(float4*)(sm.Z + r * STF + c) = v;
                }
            }
            __syncthreads();

            {
                u64 ga[18];
#pragma unroll
                for (int q = 0; q < 18; q++) ga[q] = 0;
                for (int m = 0; m < 5; m++) {
                    const float* feat;
                    if (m == 0) feat = sm.Z;
                    else {
                        int s = (m - 1) >> 1;
                        int second = (m - 1) & 1;
                        const float* src = second ? sm.Da : sm.Z;
                        float* dst = second ? sm.Db : sm.Da;
                        spmm2(sm.St2[s], src, dst,
                              second ? sm.Z : (const float*)0,
                              CC, rbase, bloc, nlo, c0);
                        __syncthreads();
                        feat = dst;
                    }
                    gemm_gate(feat, WG + (size_t)m * CC * 128,
                              kbeg, kend, colg, rbase, ga);
                }
                // reduce k-halves via scratch
                __syncthreads();
                if (tid >= 256) {
                    u64* s = scr + (size_t)(tid - 256) * 18;
#pragma unroll
                    for (int q = 0; q < 18; q++) s[q] = ga[q];
                }
                __syncthreads();
                if (tid < 256) {
                    const u64* s = scr + (size_t)tid * 18;
#pragma unroll
                    for (int q = 0; q < 18; q++) add2(ga[q], s[q]);
                    float4 bv = *(const float4*)(BG + 4 * colg);
#pragma unroll
                    for (int i = 0; i < 9; i++) {
                        float2 p0 = up2(ga[2 * i]), p1 = up2(ga[2 * i + 1]);
                        float4 o;
                        o.x = sigm(p0.x + bv.x); o.y = sigm(p0.y + bv.y);
                        o.z = sigm(p1.x + bv.z); o.w = sigm(p1.y + bv.w);
                        *(float4*)(sm.OUT + (rbase + i) * STF + 4 * colg) = o;
                    }
                }
            }
            __syncthreads();

            // ============ CANDIDATE dconv ============
            if (cell == 0) {
                for (int j = tid; j < RB * 24; j += THREADS) {
                    int r = j / 24, c = 4 * (j - 24 * r);
                    float4 v;
                    if (c < DIMX) {
                        v = *(const float4*)(sm.X + r * STX + c);
                    } else {
                        float4 h4 = *(const float4*)(sm.hA + r * STH + (c - DIMX));
                        float4 rr = *(const float4*)(sm.OUT + r * STF + (c - DIMX));
                        v = make_float4(h4.x * rr.x, h4.y * rr.y,
                                        h4.z * rr.z, h4.w * rr.w);
                    }
                    *(float4*)(sm.Z + r * STF + c) = v;
                }
            } else {
                for (int j = tid; j < RB * 32; j += THREADS) {
                    int r = j >> 5, c = 4 * (j & 31);
                    float4 v;
                    if (c < HIDN) {
                        v = *(const float4*)(sm.hA + r * STH + c);
                    } else {
                        float4 h4 = *(const float4*)(sm.hB + r * STH + (c - HIDN));
                        float4 rr = *(const float4*)(sm.OUT + r * STF + (c - HIDN));
                        v = make_float4(h4.x * rr.x, h4.y * rr.y,
                                        h4.z * rr.z, h4.w * rr.w);
                    }
                    *(float4*)(sm.Z + r * STF + c) = v;
                }
            }
            __syncthreads();

            {
                u64 ca[9];
#pragma unroll
                for (int q = 0; q < 9; q++) ca[q] = 0;
                for (int m = 0; m < 5; m++) {
                    const float* feat;
                    if (m == 0) feat = sm.Z;
                    else {
                        int s = (m - 1) >> 1;
                        int second = (m - 1) & 1;
                        const float* src = second ? sm.Da : sm.Z;
                        float* dst = second ? sm.Db : sm.Da;
                        spmm2(sm.St2[s], src, dst,
                              second ? sm.Z : (const float*)0,
                              CC, rbase, bloc, nlo, c0);
                        __syncthreads();
                        feat = dst;
                    }
                    gemm_cand(feat, WC + (size_t)m * CC * 64,
                              kbeg, kend, colg, rbase, ca);
                }
                __syncthreads();
                if (tid >= 256) {
                    u64* s = scr + (size_t)(tid - 256) * 9;
#pragma unroll
                    for (int q = 0; q < 9; q++) s[q] = ca[q];
                }
                __syncthreads();
                if (tid < 256) {
                    const u64* s = scr + (size_t)tid * 9;
#pragma unroll
                    for (int q = 0; q < 9; q++) add2(ca[q], s[q]);
                    float2 bv = *(const float2*)(BC + 2 * colg);
#pragma unroll
                    for (int i = 0; i < 9; i++) {
                        float2 p = up2(ca[i]);
                        float2 o = make_float2(tanh_(p.x + bv.x),
                                               tanh_(p.y + bv.y));
                        *(float2*)(sm.CB + (rbase + i) * STH + 2 * colg) = o;
                    }
                }
            }
            __syncthreads();

            // ============ GRU update: h = c + u*(h - c) ============
            for (int j = tid; j < RB * 32; j += THREADS) {
                int r = j >> 5, c = 2 * (j & 31);
                float2 h2 = *(const float2*)(H + r * STH + c);
                float2 c2 = *(const float2*)(sm.CB + r * STH + c);
                float2 u2 = *(const float2*)(sm.OUT + r * STF + HIDN + c);
                float2 nh = make_float2(c2.x + u2.x * (h2.x - c2.x),
                                        c2.y + u2.y * (h2.y - c2.y));
                *(float2*)(H + r * STH + c) = nh;
            }
            __syncthreads();
        } // cell
    } // t

    // ---- epilogue: logits = relu(hB) @ fc_w + fc_b; out[b] = max over nodes ----
    if (tid < RB) {
        float acc = fcb[0];
#pragma unroll
        for (int c = 0; c < HIDN; c++)
            acc += fmaxf(sm.hB[tid * STH + c], 0.f) * fcw[c];
        sm.Z[tid] = acc;
    }
    __syncthreads();
    if (tid < NB) {
        float mx = -3.4e38f;
#pragma unroll
        for (int n = 0; n < NNODE; n++)
            mx = fmaxf(mx, sm.Z[tid * NNODE + n]);
        out[bbase + tid] = mx;
    }
}

extern "C" void kernel_launch(void* const* d_in, const int* in_sizes, int n_in,
                              void* d_out, int out_size)
{
    (void)in_sizes; (void)n_in; (void)out_size;
    const size_t shbytes = sizeof(Smem);
    cudaFuncSetAttribute(dcrnn_kernel,
                         cudaFuncAttributeMaxDynamicSharedMemorySize,
                         (int)shbytes);
    dcrnn_kernel<<<NBLK, THREADS, shbytes>>>(
        (const float*)d_in[0],  (const float*)d_in[1],
        (const float*)d_in[2],  (const float*)d_in[3],
        (const float*)d_in[4],  (const float*)d_in[5],
        (const float*)d_in[6],  (const float*)d_in[7],
        (const float*)d_in[8],  (const float*)d_in[9],
        (const float*)d_in[10], (const float*)d_in[11],
        (float*)d_out);
}